// round 11
// baseline (speedup 1.0000x reference)
#include <cuda_runtime.h>

using ull = unsigned long long;

// ---------- packed f32x2 + MUFU helpers ----------
__device__ __forceinline__ ull pk2(float lo, float hi) {
    ull r; asm("mov.b64 %0, {%1, %2};" : "=l"(r) : "f"(lo), "f"(hi)); return r;
}
__device__ __forceinline__ void upk2(ull v, float& lo, float& hi) {
    asm("mov.b64 {%0, %1}, %2;" : "=f"(lo), "=f"(hi) : "l"(v));
}
__device__ __forceinline__ ull fma2(ull a, ull b, ull c) {
    ull d; asm("fma.rn.f32x2 %0, %1, %2, %3;" : "=l"(d) : "l"(a), "l"(b), "l"(c)); return d;
}
__device__ __forceinline__ ull add2(ull a, ull b) {
    ull d; asm("add.rn.f32x2 %0, %1, %2;" : "=l"(d) : "l"(a), "l"(b)); return d;
}
__device__ __forceinline__ float tanhf_hw(float x) {
    float y; asm("tanh.approx.f32 %0, %1;" : "=f"(y) : "f"(x)); return y;
}

#define HID 10

// Gate-split across two warps of a 64-thread block, 3 elems/block:
//   warp0 lanes 0-29: packed (i,f) rows for unit j of elem grp + cell + h-publish
//   warp1 lanes 0-29: packed (g,o) rows for unit j of elem grp
//   spare lanes (w0:30,31 / w1:30,31): fc output head as their "gate row"
//     (y_t emerges from the NEXT step's dot; epilogue computes y_{S-1})
// Join and publish via block smem + 2 __syncthreads()/step (single-buffer
// safe: every RAW/WAR pair is separated by one of the two barriers).
// Sigmoid = 0.5*(1+tanh(x/2)) with 0.5 folded into i/f/o weight rows.
// -> 2732 warps (4.6/SMSP) at ~20 inst/elem-step.
__global__ void __launch_bounds__(64, 8)
lstm_split_kernel(const float* __restrict__ x,
                  const float* __restrict__ w_ih,
                  const float* __restrict__ w_hh,
                  const float* __restrict__ b_ih,
                  const float* __restrict__ b_hh,
                  const float* __restrict__ fc_w,
                  const float* __restrict__ fc_b,
                  float* __restrict__ out,
                  int S, int B)
{
    __shared__ __align__(16) ull dupH[3][HID];  // (h,h) duplicated pairs per grp
    __shared__ float2 goBuf[3][HID];            // (ga, oa) per grp, unit j

    const int tid  = threadIdx.x;
    const int wid  = tid >> 5;        // 0: (i,f)+cell ; 1: (g,o)
    const int lane = tid & 31;
    const int wg   = blockIdx.x;

    const bool isHead = (lane >= 30);
    int grp, j;
    if (!isHead) { grp = lane / HID; j = lane - grp * HID; }
    else         { grp = (wid == 0) ? (lane - 30) : 2; j = HID - 1; }

    int b = wg * 3 + grp;
    const bool okB = (b < B);
    if (b >= B) b = B - 1;            // safe-load clamp

    // ---- per-lane packed weights ----
    ull wh[HID], wx, bias;
    if (isHead) {                     // fc head row: y rides the gate dot
#pragma unroll
        for (int k = 0; k < HID; ++k) wh[k] = pk2(fc_w[k], fc_w[k]);
        wx   = 0ull;
        bias = pk2(fc_b[0], fc_b[0]);
    } else if (wid == 0) {            // (i,f) rows, 0.5 sigmoid-fold
#pragma unroll
        for (int k = 0; k < HID; ++k)
            wh[k] = pk2(0.5f * w_hh[j * HID + k],
                        0.5f * w_hh[(HID + j) * HID + k]);
        wx   = pk2(0.5f * w_ih[j], 0.5f * w_ih[HID + j]);
        bias = pk2(0.5f * (b_ih[j] + b_hh[j]),
                   0.5f * (b_ih[HID + j] + b_hh[HID + j]));
    } else {                          // (g,o) rows: g raw, o 0.5-folded
#pragma unroll
        for (int k = 0; k < HID; ++k)
            wh[k] = pk2(       w_hh[(2 * HID + j) * HID + k],
                        0.5f * w_hh[(3 * HID + j) * HID + k]);
        wx   = pk2(w_ih[2 * HID + j], 0.5f * w_ih[3 * HID + j]);
        bias = pk2(        b_ih[2 * HID + j] + b_hh[2 * HID + j],
                   0.5f * (b_ih[3 * HID + j] + b_hh[3 * HID + j]));
    }

    // head-writer predicate: w0 lanes 30,31 -> grps 0,1; w1 lane 30 -> grp 2
    const bool wrY   = isHead && okB && !(wid == 1 && lane == 31);
    const bool stsGO = (wid == 1) && !isHead;
    const bool stsH  = (wid == 0) && !isHead;

    // ---- state ----
    ull hd[HID];
#pragma unroll
    for (int k = 0; k < HID; ++k) hd[k] = 0ull;
    float c = 0.f;

    // ---- x prefetch: 4 in flight, pointer-bumped, blind (tail peeled) ----
    float xb[4];
#pragma unroll
    for (int i = 0; i < 4; ++i) xb[i] = __ldg(x + (size_t)i * B + b);
    const float* xp = x + (size_t)4 * B + b;
    float* pY = out + b;              // head: y_{s-1} stored at step s

#define STEP(XT, DO_Y)                                                       \
    {                                                                        \
        const ull xd = pk2((XT), (XT));                                      \
        ull a0 = fma2(xd, wx, bias);                                         \
        ull a1 = fma2(hd[1], wh[1], 0ull);                                   \
        _Pragma("unroll")                                                    \
        for (int k = 0; k < HID; k += 2) a0 = fma2(hd[k], wh[k], a0);        \
        _Pragma("unroll")                                                    \
        for (int k = 3; k < HID; k += 2) a1 = fma2(hd[k], wh[k], a1);        \
        float lo, hi;                                                        \
        upk2(add2(a0, a1), lo, hi);                                          \
        if ((DO_Y) && wrY) { *pY = lo; pY += B; }  /* head: lo == y_{s-1} */ \
        const float t0 = tanhf_hw(lo);                                       \
        const float t1 = tanhf_hw(hi);                                       \
        float ia = 0.f, fa = 0.f;                                            \
        if (wid == 1) {                                                      \
            const float oa = fmaf(0.5f, t1, 0.5f);                           \
            if (stsGO) goBuf[grp][j] = make_float2(t0, oa);                  \
        } else {                                                             \
            ia = fmaf(0.5f, t0, 0.5f);                                       \
            fa = fmaf(0.5f, t1, 0.5f);                                       \
        }                                                                    \
        __syncthreads();                                                     \
        if (wid == 0) {                                                      \
            const float2 go = goBuf[grp][j];                                 \
            const float cn = fmaf(ia, go.x, fa * c);                         \
            c = cn;                                                          \
            const float hn = go.y * tanhf_hw(cn);                            \
            if (stsH) dupH[grp][j] = pk2(hn, hn);                            \
        }                                                                    \
        __syncthreads();                                                     \
        _Pragma("unroll")                                                    \
        for (int p = 0; p < 5; ++p) {                                        \
            const ulonglong2 v = *(const ulonglong2*)&dupH[grp][2 * p];      \
            hd[2 * p]     = v.x;                                             \
            hd[2 * p + 1] = v.y;                                             \
        }                                                                    \
    }

    // prologue: steps 0..3 (step 0 has no y to write)
    { const float xt = xb[0]; xb[0] = __ldg(xp); xp += B; STEP(xt, 0) }
    { const float xt = xb[1]; xb[1] = __ldg(xp); xp += B; STEP(xt, 1) }
    { const float xt = xb[2]; xb[2] = __ldg(xp); xp += B; STEP(xt, 1) }
    { const float xt = xb[3]; xb[3] = __ldg(xp); xp += B; STEP(xt, 1) }

    // main: blind prefetch stays in-bounds (last iter t=S-8 fetches x[S-1])
    for (int t = 4; t < S - 4; t += 4) {
#pragma unroll
        for (int u = 0; u < 4; ++u) {
            const float xt = xb[u];
            xb[u] = __ldg(xp);
            xp += B;
            STEP(xt, 1)
        }
    }

    // tail: last 4 steps, no prefetch
#pragma unroll
    for (int u = 0; u < 4; ++u) {
        const float xt = xb[u];
        STEP(xt, 1)
    }
#undef STEP

    // epilogue: y_{S-1} from the final h (head lanes only)
    if (wrY) {
        ull a0 = fma2(hd[0], wh[0], bias);
        ull a1 = fma2(hd[1], wh[1], 0ull);
#pragma unroll
        for (int k = 2; k < HID; k += 2) a0 = fma2(hd[k], wh[k], a0);
#pragma unroll
        for (int k = 3; k < HID; k += 2) a1 = fma2(hd[k], wh[k], a1);
        float lo, hi;
        upk2(add2(a0, a1), lo, hi);
        *pY = lo;
    }
}

extern "C" void kernel_launch(void* const* d_in, const int* in_sizes, int n_in,
                              void* d_out, int out_size)
{
    const float* x    = (const float*)d_in[0];
    const float* w_ih = (const float*)d_in[1];
    const float* w_hh = (const float*)d_in[2];
    const float* b_ih = (const float*)d_in[3];
    const float* b_hh = (const float*)d_in[4];
    const float* fc_w = (const float*)d_in[5];
    const float* fc_b = (const float*)d_in[6];
    float* out = (float*)d_out;

    const int B = 4096;
    const int S = in_sizes[0] / B;   // 2048

    // 3 elems per 64-thread (2-warp) block -> 2732 warps = 4.6/SMSP
    const int blocks = (B + 2) / 3;  // 1366

    lstm_split_kernel<<<blocks, 64>>>(x, w_ih, w_hh, b_ih, b_hh,
                                      fc_w, fc_b, out, S, B);
}